// round 4
// baseline (speedup 1.0000x reference)
#include <cuda_runtime.h>
#include <cuda_fp16.h>
#include <math.h>
#include <stdint.h>

// Problem constants
#define B_    512
#define TENC  140
#define E_    256
#define H_    512
#define O_    64
#define TOUT  280
#define NSTEP 140
#define ROWS_ENC (B_*TENC)   // 71680

// Persistent kernel geometry: 256 CTAs = 8 row-groups x 32 col-CTAs, 2 CTAs/SM
#define WG_BYTES (3 * 16 * 2048)          // 98304: 3 gates x 16 j-rows x 1024 halves
#define AS_BYTES (2 * 64 * 128)           // 16384: 2 bufs x 64 rows x 64 halves
#define SMEM_TOTAL_BYTES (WG_BYTES + AS_BYTES)   // 114688 (112KB) -> 2 CTAs/SM

// ---------------------------------------------------------------------------
// Device scratch (static globals; no runtime allocation allowed)
// ---------------------------------------------------------------------------
__device__ __half d_eh[2][B_ * 1024];        // [buf][row][0:512 e | 512:1024 h] fp16
__device__ float  d_h32[2][B_ * H_];         // fp32 hidden state, double buffered
__device__ __half d_Wg[3 * H_ * 1024];       // 1536 x 1024: [w_ih | w_hh] fused by K
__device__ __half d_WA[(H_ + O_) * H_];      // 576 x 512: [emb_W@out_W ; reg_W@out_W]
__device__ float  d_bA[H_ + O_];             // fused biases
__device__ __half d_x0[B_ * E_];             // x0 = encoder_outputs[:, -1, :] fp16
__device__ __half d_embW[H_ * E_];           // emb_W fp16 (step-0 path)
__device__ __half d_regW[O_ * E_];           // reg_W fp16 (encoder head)
__device__ __half d_enc16[(size_t)ROWS_ENC * E_]; // encoder outputs fp16

// Row-group barriers (8 groups of 32 CTAs), one cache line each
struct Bar { unsigned cnt; unsigned gen; unsigned pad[30]; };
__device__ Bar d_bars[8];

// ---------------------------------------------------------------------------
// mma / ldmatrix helpers
// ---------------------------------------------------------------------------
__device__ __forceinline__ void mma16816(float c[4], const uint32_t a[4], const uint32_t b[2]) {
    asm volatile(
        "mma.sync.aligned.m16n8k16.row.col.f32.f16.f16.f32 "
        "{%0,%1,%2,%3}, {%4,%5,%6,%7}, {%8,%9}, {%0,%1,%2,%3};\n"
        : "+f"(c[0]), "+f"(c[1]), "+f"(c[2]), "+f"(c[3])
        : "r"(a[0]), "r"(a[1]), "r"(a[2]), "r"(a[3]), "r"(b[0]), "r"(b[1]));
}

__device__ __forceinline__ void ldsm_x4(uint32_t r[4], uint32_t saddr) {
    asm volatile("ldmatrix.sync.aligned.m8n8.x4.shared.b16 {%0,%1,%2,%3}, [%4];"
                 : "=r"(r[0]), "=r"(r[1]), "=r"(r[2]), "=r"(r[3]) : "r"(saddr));
}
__device__ __forceinline__ void ldsm_x2(uint32_t r[2], uint32_t saddr) {
    asm volatile("ldmatrix.sync.aligned.m8n8.x2.shared.b16 {%0,%1}, [%2];"
                 : "=r"(r[0]), "=r"(r[1]) : "r"(saddr));
}

// legacy scalar frag loads (for the one-shot gemmA kernel)
__device__ __forceinline__ void load_a_frag(uint32_t a[4], const __half* As, int ld,
                                            int row0, int k0, int grp, int qp) {
    const __half* p = As + (row0 + grp) * ld + k0 + qp * 2;
    a[0] = *(const uint32_t*)(p);
    a[1] = *(const uint32_t*)(p + 8 * ld);
    a[2] = *(const uint32_t*)(p + 8);
    a[3] = *(const uint32_t*)(p + 8 * ld + 8);
}
__device__ __forceinline__ void load_b_frag(uint32_t b[2], const __half* Bs, int ld,
                                            int n0, int k0, int grp, int qp) {
    const __half* p = Bs + (n0 + grp) * ld + k0 + qp * 2;
    b[0] = *(const uint32_t*)(p);
    b[1] = *(const uint32_t*)(p + 8);
}

__device__ __forceinline__ float sigf(float x) { return 1.0f / (1.0f + __expf(-x)); }

// cp.async helpers
__device__ __forceinline__ void cp_async16(void* s, const void* g) {
    unsigned sa = (unsigned)__cvta_generic_to_shared(s);
    asm volatile("cp.async.ca.shared.global [%0], [%1], 16;\n" :: "r"(sa), "l"(g));
}
__device__ __forceinline__ void cp_commit() { asm volatile("cp.async.commit_group;\n"); }
__device__ __forceinline__ void cp_wait0()  { asm volatile("cp.async.wait_group 0;\n"); }

// 32-CTA row-group barrier. target = monotonically increasing generation.
__device__ __forceinline__ void group_barrier(int rb, unsigned target) {
    __syncthreads();
    if (threadIdx.x == 0) {
        __threadfence();
        unsigned a = atomicAdd(&d_bars[rb].cnt, 1);
        if (a == 31) {
            d_bars[rb].cnt = 0;
            __threadfence();
            atomicAdd(&d_bars[rb].gen, 1);
        } else {
            unsigned g;
            do {
                __nanosleep(32);
                asm volatile("ld.volatile.global.u32 %0, [%1];" : "=r"(g) : "l"(&d_bars[rb].gen));
            } while (g < target);
        }
        __threadfence();
    }
    __syncthreads();
}

// ---------------------------------------------------------------------------
// prep: weight fusion + fp16 conversions + barrier reset (one launch)
// ---------------------------------------------------------------------------
__global__ void prep_kernel(const float* __restrict__ enc,  const float* __restrict__ ehid,
                            const float* __restrict__ embW, const float* __restrict__ embB,
                            const float* __restrict__ wih,  const float* __restrict__ whh,
                            const float* __restrict__ outW, const float* __restrict__ outB,
                            const float* __restrict__ regW, const float* __restrict__ regB) {
    long long gid0 = (long long)blockIdx.x * blockDim.x + threadIdx.x;
    if (gid0 < 8) { d_bars[gid0].cnt = 0; d_bars[gid0].gen = 0; }

    const long long N0  = (long long)ROWS_ENC * E_;
    const long long N1  = N0 + (long long)B_ * E_;
    const long long N2  = N1 + 1536LL * 1024;
    const long long N3  = N2 + 576LL * 512;
    const long long N3b = N3 + 576;
    const long long N4  = N3b + (long long)O_ * E_;
    const long long N5  = N4 + (long long)B_ * H_;
    const long long N6  = N5 + (long long)H_ * E_;

    for (long long i = gid0; i < N6; i += (long long)gridDim.x * blockDim.x) {
        if (i < N0) {
            d_enc16[i] = __float2half(enc[i]);
        } else if (i < N1) {
            long long k = i - N0; int b = (int)(k >> 8), c = (int)(k & 255);
            d_x0[k] = __float2half(enc[(long long)b * TENC * E_ + 139 * E_ + c]);
        } else if (i < N2) {
            long long k = i - N1; int j = (int)(k >> 10), c = (int)(k & 1023);
            float v = (c < 512) ? wih[j * 512 + c] : whh[j * 512 + c - 512];
            d_Wg[k] = __float2half(v);
        } else if (i < N3) {
            long long k = i - N2; int j = (int)(k >> 9), c = (int)(k & 511);
            float s = 0.f;
            if (j < 512) { for (int m = 0; m < E_; ++m) s += embW[j * E_ + m] * outW[m * H_ + c]; }
            else { int o = j - 512; for (int m = 0; m < E_; ++m) s += regW[o * E_ + m] * outW[m * H_ + c]; }
            d_WA[k] = __float2half(s);
        } else if (i < N3b) {
            int j = (int)(i - N3);
            float s = 0.f;
            if (j < 512) { for (int m = 0; m < E_; ++m) s += embW[j * E_ + m] * outB[m]; s += embB[j]; }
            else { int o = j - 512; for (int m = 0; m < E_; ++m) s += regW[o * E_ + m] * outB[m]; s += regB[o]; }
            d_bA[j] = s;
        } else if (i < N4) {
            long long k = i - N3b; d_regW[k] = __float2half(regW[k]);
        } else if (i < N5) {
            long long k = i - N4; int b = (int)(k >> 9), c = (int)(k & 511);
            float v = ehid[k];
            d_h32[0][k] = v;
            d_eh[0][b * 1024 + 512 + c] = __float2half(v);
        } else {
            long long k = i - N5; d_embW[k] = __float2half(embW[k]);
        }
    }
}

// ---------------------------------------------------------------------------
// Generic fp16 GEMM (one-shot encoder head and e0)
// ---------------------------------------------------------------------------
__global__ __launch_bounds__(256) void gemmA_kernel(
    const __half* __restrict__ A, int lda,
    const __half* __restrict__ Bw, int ldb,
    const float* __restrict__ bias, int K,
    __half* __restrict__ e_out, float* __restrict__ dec_out,
    int t_dec, int enc_mode)
{
    __shared__ __align__(16) __half As[64 * 40];
    __shared__ __align__(16) __half Bs[32 * 40];

    const int tid = threadIdx.x;
    const int m0 = blockIdx.y * 64, n0 = blockIdx.x * 32;
    const int lane = tid & 31, warp = tid >> 5;
    const int wm = warp >> 1, wn = warp & 1;
    const int grp = lane >> 2, qp = lane & 3;

    float c[2][4] = {};
    const int nch = K >> 5;

    for (int kc = 0; kc < nch; ++kc) {
        const int k0 = kc * 32;
        __syncthreads();
        { int r = tid >> 2, v = tid & 3;
          *(uint4*)&As[r * 40 + v * 8] = *(const uint4*)&A[(size_t)(m0 + r) * lda + k0 + v * 8]; }
        if (tid < 128) { int r = tid >> 2, v = tid & 3;
          *(uint4*)&Bs[r * 40 + v * 8] = *(const uint4*)&Bw[(size_t)(n0 + r) * ldb + k0 + v * 8]; }
        __syncthreads();
#pragma unroll
        for (int kk = 0; kk < 32; kk += 16) {
            uint32_t a[4];
            load_a_frag(a, As, 40, wm * 16, kk, grp, qp);
            uint32_t b[2];
            load_b_frag(b, Bs, 40, wn * 16 + 0, kk, grp, qp);
            mma16816(c[0], a, b);
            load_b_frag(b, Bs, 40, wn * 16 + 8, kk, grp, qp);
            mma16816(c[1], a, b);
        }
    }

    const int rbase = m0 + wm * 16 + grp;
    const int cbase = n0 + wn * 16 + qp * 2;
#pragma unroll
    for (int nb = 0; nb < 2; ++nb)
#pragma unroll
        for (int i = 0; i < 4; ++i) {
            int row = rbase + (i >> 1) * 8;
            int col = cbase + nb * 8 + (i & 1);
            float v = c[nb][i] + bias[col];
            if (enc_mode) {
                int b = row / 140, tt = row - b * 140;
                dec_out[(size_t)b * TOUT * O_ + tt * O_ + col] = v;
            } else if (col < H_) {
                e_out[(size_t)row * 1024 + col] = __float2half(fmaxf(v, 0.0f));
            } else {
                dec_out[(size_t)row * TOUT * O_ + t_dec * O_ + (col - H_)] = v;
            }
        }
}

// ---------------------------------------------------------------------------
// Persistent RNN kernel: 256 CTAs (8 row-groups x 32 col-CTAs), 2 CTAs/SM.
// Weight slice (96KB, XOR-swizzled) SMEM-resident; activations cp.async
// double-buffered; phase-A WA fragments streamed from L2 via LDG.
//
// CTA (rb, cb):
//   Phase B: gates for rows [rb*64,+64), j-cols [cb*16,+16), K=1024 -> h_{t+1}
//   Phase A (cb<18): [e|dec] rows rb, out-cols [cb*32,+32), K=512
// ---------------------------------------------------------------------------
extern __shared__ char smc[];

__global__ __launch_bounds__(256, 2) void persist_kernel(
    const float* __restrict__ bih, const float* __restrict__ bhh,
    float* __restrict__ out)
{
    const int tid = threadIdx.x;
    const int cid = blockIdx.x;
    const int rb = cid >> 5, cb = cid & 31;
    const int lane = tid & 31, warp = tid >> 5;
    const int wm = warp >> 1, wn = warp & 1;          // 4 x 2 warps
    const int grp = lane >> 2, qp = lane & 3;
    const int m0g = rb * 64;

    const uint32_t wg_base = (uint32_t)__cvta_generic_to_shared(smc);
    const uint32_t as_base = (uint32_t)__cvta_generic_to_shared(smc + WG_BYTES);

    // A-frag ldmatrix per-thread constants (row stride 128B, XOR swizzle)
    const int a_lrow = lane & 15;
    const uint32_t a_rowbase = as_base + (uint32_t)(wm * 16 + a_lrow) * 128;
    const int a_cc = (lane >> 4) << 4;                 // 0 or 16 bytes
    const int a_rx = (a_lrow & 7) << 4;                // row xor

    // B-frag (phase B) per-thread constants (row stride 2048B, XOR swizzle)
    const int brow = wn * 8 + (lane & 7);
    const int b_cc = ((lane >> 3) & 1) << 4;
    const int b_rx = (lane & 7) << 4;
    uint32_t b_rowbase[3];
#pragma unroll
    for (int g = 0; g < 3; ++g)
        b_rowbase[g] = wg_base + (uint32_t)(g * 16 + brow) * 2048;

    // ---- Load this CTA's weight slice once (3 x 16 rows x 1024 halves) ----
    for (int idx = tid; idx < 3 * 16 * 128; idx += 256) {
        int r = idx >> 7, v = idx & 127;               // r: gate*16+jr
        int g = r >> 4, jr = r & 15;
        cp_async16(smc + r * 2048 + ((v * 16) ^ ((jr & 7) << 4)),
                   &d_Wg[(size_t)(g * 512 + cb * 16 + jr) * 1024 + v * 8]);
    }
    cp_commit(); cp_wait0(); __syncthreads();

    // cp.async A-chunk helper indices
    const int ld_r = tid >> 3, ld_v = tid & 7;         // idx and idx+256 rows
    const int ld_r2 = (tid + 256) >> 3, ld_v2 = tid & 7;
    char* as0 = smc + WG_BYTES;

    unsigned gen = 0;
    int cur = 0;
    for (int t = 0; t < NSTEP; ++t) {
        const int nxt = cur ^ 1;

        // ================= Phase B: gate GEMM + GRU epilogue ================
        {
            const __half* A = d_eh[cur];
            float cR[4] = {}, cZ[4] = {}, cNi[4] = {}, cNh[4] = {};

            // preload chunk 0
            cp_async16(as0 + ld_r * 128 + ((ld_v * 16) ^ ((ld_r & 7) << 4)),
                       &A[(size_t)(m0g + ld_r) * 1024 + ld_v * 8]);
            cp_async16(as0 + ld_r2 * 128 + ((ld_v2 * 16) ^ ((ld_r2 & 7) << 4)),
                       &A[(size_t)(m0g + ld_r2) * 1024 + ld_v2 * 8]);
            cp_commit();

#pragma unroll 1
            for (int kc = 0; kc < 16; ++kc) {
                cp_wait0();
                __syncthreads();
                if (kc < 15) {
                    char* buf = as0 + (((kc + 1) & 1) << 13);
                    cp_async16(buf + ld_r * 128 + ((ld_v * 16) ^ ((ld_r & 7) << 4)),
                               &A[(size_t)(m0g + ld_r) * 1024 + (kc + 1) * 64 + ld_v * 8]);
                    cp_async16(buf + ld_r2 * 128 + ((ld_v2 * 16) ^ ((ld_r2 & 7) << 4)),
                               &A[(size_t)(m0g + ld_r2) * 1024 + (kc + 1) * 64 + ld_v2 * 8]);
                    cp_commit();
                }
                const uint32_t abase = a_rowbase + (uint32_t)((kc & 1) << 13);
                const int kw2 = kc * 128;              // chunk byte offset in weight rows
#pragma unroll
                for (int kk4 = 0; kk4 < 4; ++kk4) {
                    const int kb = kk4 * 32;
                    uint32_t a[4], b0[2], b1[2], b2[2];
                    ldsm_x4(a,  abase + (uint32_t)((a_cc + kb) ^ a_rx));
                    ldsm_x2(b0, b_rowbase[0] + (uint32_t)((b_cc + kw2 + kb) ^ b_rx));
                    ldsm_x2(b1, b_rowbase[1] + (uint32_t)((b_cc + kw2 + kb) ^ b_rx));
                    ldsm_x2(b2, b_rowbase[2] + (uint32_t)((b_cc + kw2 + kb) ^ b_rx));
                    mma16816(cR, a, b0);
                    mma16816(cZ, a, b1);
                    if (kc < 8) mma16816(cNi, a, b2);
                    else        mma16816(cNh, a, b2);
                }
            }

            const float* h32c = d_h32[cur];
            float* h32n = d_h32[nxt];
            __half* ehn = d_eh[nxt];
            const int rbase = m0g + wm * 16 + grp;
            const int jbase = cb * 16 + wn * 8 + qp * 2;
#pragma unroll
            for (int i = 0; i < 4; ++i) {
                int row = rbase + (i >> 1) * 8;
                int j = jbase + (i & 1);
                float r = sigf(cR[i] + bih[j] + bhh[j]);
                float z = sigf(cZ[i] + bih[512 + j] + bhh[512 + j]);
                float nn = tanhf(cNi[i] + bih[1024 + j] + r * (cNh[i] + bhh[1024 + j]));
                float ho = h32c[row * 512 + j];
                float hv = (1.0f - z) * nn + z * ho;
                h32n[row * 512 + j] = hv;
                ehn[(size_t)row * 1024 + 512 + j] = __float2half(hv);
            }
        }
        ++gen; group_barrier(rb, gen);

        // ============ Phase A: [e|dec] = h_{t+1} @ WA^T + bA ================
        if (cb < 18) {
            const __half* A = &d_eh[nxt][512];   // h half, row stride 1024
            const int n0c = cb * 32;
            float cc[2][4] = {};

            // WA fragment source pointers (global, L2-resident)
            const __half* pw[2];
#pragma unroll
            for (int nb = 0; nb < 2; ++nb)
                pw[nb] = d_WA + (size_t)(n0c + wn * 16 + nb * 8 + grp) * 512 + qp * 2;

            uint32_t Breg[2][4][4];   // [buf][kk4][nb*2 + {0,1}]

            // preload A chunk 0 + WA chunk 0 frags
            cp_async16(as0 + ld_r * 128 + ((ld_v * 16) ^ ((ld_r & 7) << 4)),
                       &A[(size_t)(m0g + ld_r) * 1024 + ld_v * 8]);
            cp_async16(as0 + ld_r2 * 128 + ((ld_v2 * 16) ^ ((ld_r2 & 7) << 4)),
                       &A[(size_t)(m0g + ld_r2) * 1024 + ld_v2 * 8]);
            cp_commit();
#pragma unroll
            for (int kk4 = 0; kk4 < 4; ++kk4)
#pragma unroll
                for (int nb = 0; nb < 2; ++nb) {
                    Breg[0][kk4][nb * 2 + 0] = *(const uint32_t*)&pw[nb][kk4 * 16];
                    Breg[0][kk4][nb * 2 + 1] = *(const uint32_t*)&pw[nb][kk4 * 16 + 8];
                }

#pragma unroll 1
            for (int kc = 0; kc < 8; ++kc) {
                cp_wait0();
                __syncthreads();
                const int cbuf = kc & 1, nbuf = cbuf ^ 1;
                if (kc < 7) {
                    char* buf = as0 + (nbuf << 13);
                    cp_async16(buf + ld_r * 128 + ((ld_v * 16) ^ ((ld_r & 7) << 4)),
                               &A[(size_t)(m0g + ld_r) * 1024 + (kc + 1) * 64 + ld_v * 8]);
                    cp_async16(buf + ld_r2 * 128 + ((ld_v2 * 16) ^ ((ld_r2 & 7) << 4)),
                               &A[(size_t)(m0g + ld_r2) * 1024 + (kc + 1) * 64 + ld_v2 * 8]);
                    cp_commit();
#pragma unroll
                    for (int kk4 = 0; kk4 < 4; ++kk4)
#pragma unroll
                        for (int nb = 0; nb < 2; ++nb) {
                            Breg[1 - cbuf][kk4][nb * 2 + 0] =
                                *(const uint32_t*)&pw[nb][(kc + 1) * 64 + kk4 * 16];
                            Breg[1 - cbuf][kk4][nb * 2 + 1] =
                                *(const uint32_t*)&pw[nb][(kc + 1) * 64 + kk4 * 16 + 8];
                        }
                }
                const uint32_t abase = a_rowbase + (uint32_t)(cbuf << 13);
#pragma unroll
                for (int kk4 = 0; kk4 < 4; ++kk4) {
                    const int kb = kk4 * 32;
                    uint32_t a[4];
                    ldsm_x4(a, abase + (uint32_t)((a_cc + kb) ^ a_rx));
                    mma16816(cc[0], a, &Breg[cbuf][kk4][0]);
                    mma16816(cc[1], a, &Breg[cbuf][kk4][2]);
                }
            }

            __half* ehn = d_eh[nxt];
            const int rbase = m0g + wm * 16 + grp;
#pragma unroll
            for (int nb = 0; nb < 2; ++nb)
#pragma unroll
                for (int i = 0; i < 4; ++i) {
                    int row = rbase + (i >> 1) * 8;
                    int j = n0c + wn * 16 + nb * 8 + qp * 2 + (i & 1);
                    float v = cc[nb][i] + d_bA[j];
                    if (j < 512) ehn[(size_t)row * 1024 + j] = __float2half(fmaxf(v, 0.0f));
                    else out[(size_t)row * TOUT * O_ + (140 + t) * O_ + (j - 512)] = v;
                }
        }
        ++gen; group_barrier(rb, gen);

        cur = nxt;
    }
}

// ---------------------------------------------------------------------------
// Launch sequence (graph-capturable, default stream)
// ---------------------------------------------------------------------------
extern "C" void kernel_launch(void* const* d_in, const int* in_sizes, int n_in,
                              void* d_out, int out_size) {
    const float* enc  = (const float*)d_in[0];
    const float* ehid = (const float*)d_in[1];
    const float* embW = (const float*)d_in[2];
    const float* embB = (const float*)d_in[3];
    const float* wih  = (const float*)d_in[4];
    const float* whh  = (const float*)d_in[5];
    const float* bih  = (const float*)d_in[6];
    const float* bhh  = (const float*)d_in[7];
    const float* outW = (const float*)d_in[8];
    const float* outB = (const float*)d_in[9];
    const float* regW = (const float*)d_in[10];
    const float* regB = (const float*)d_in[11];
    float* out = (float*)d_out;

    void* sym;
    cudaGetSymbolAddress(&sym, d_eh);    __half* p_eh   = (__half*)sym;
    cudaGetSymbolAddress(&sym, d_x0);    __half* p_x0   = (__half*)sym;
    cudaGetSymbolAddress(&sym, d_embW);  __half* p_embW = (__half*)sym;
    cudaGetSymbolAddress(&sym, d_regW);  __half* p_regW = (__half*)sym;
    cudaGetSymbolAddress(&sym, d_enc16); __half* p_enc  = (__half*)sym;

    cudaFuncSetAttribute(persist_kernel,
                         cudaFuncAttributeMaxDynamicSharedMemorySize, SMEM_TOTAL_BYTES);

    // 1) Prep: conversions + weight fusion + barrier reset
    prep_kernel<<<4096, 256>>>(enc, ehid, embW, embB, wih, whh, outW, outB, regW, regB);

    // 2) Encoder regression head: out[:, 0:140, :]
    gemmA_kernel<<<dim3(2, 1120), 256>>>(p_enc, E_, p_regW, E_, regB, E_,
                                         nullptr, out, 0, 1);

    // 3) Step 0: e0 = relu(x0 @ emb_W^T + emb_b)
    gemmA_kernel<<<dim3(16, 8), 256>>>(p_x0, E_, p_embW, E_, embB, E_,
                                       p_eh, nullptr, 0, 0);

    // 4) All 140 GRU steps in one persistent kernel (256 CTAs, 2/SM)
    persist_kernel<<<256, 256, SMEM_TOTAL_BYTES>>>(bih, bhh, out);
}

// round 5
// speedup vs baseline: 1.2344x; 1.2344x over previous
#include <cuda_runtime.h>
#include <cuda_fp16.h>
#include <math.h>
#include <stdint.h>

// Problem constants
#define B_    512
#define TENC  140
#define E_    256
#define H_    512
#define O_    64
#define TOUT  280
#define NSTEP 140
#define ROWS_ENC (B_*TENC)   // 71680

// Persistent kernel: 128 CTAs = 8 row-groups x 16 col-CTAs, 1 CTA/SM
#define WG_BYTES   (96 * 2048)              // 196608: 3 gates x 32 j-rows x 1024 halves (swizzled)
#define ASTG_BYTES 8192                     // one A stage: 64 rows x 64 halves
#define SMEM_TOTAL_BYTES (WG_BYTES + 4 * ASTG_BYTES)   // 229376

// ---------------------------------------------------------------------------
// Device scratch (static globals; no runtime allocation allowed)
// ---------------------------------------------------------------------------
__device__ __half d_eh[2][B_ * 1024];        // [buf][row][0:512 e | 512:1024 h] fp16
__device__ float  d_h32[2][B_ * H_];         // (init only; persistent kernel keeps h in regs)
__device__ __half d_Wg[3 * H_ * 1024];       // 1536 x 1024: [w_ih | w_hh] fused by K
__device__ __half d_WA[(H_ + O_) * H_];      // 576 x 512: [emb_W@out_W ; reg_W@out_W]
__device__ float  d_bA[H_ + O_];             // fused biases
__device__ __half d_x0[B_ * E_];             // x0 = encoder_outputs[:, -1, :] fp16
__device__ __half d_embW[H_ * E_];           // emb_W fp16 (step-0 path)
__device__ __half d_regW[O_ * E_];           // reg_W fp16 (encoder head)
__device__ __half d_enc16[(size_t)ROWS_ENC * E_]; // encoder outputs fp16

// Row-group barriers (8 groups of 16 CTAs), one cache line each
struct Bar { unsigned cnt; unsigned gen; unsigned pad[30]; };
__device__ Bar d_bars[8];

// ---------------------------------------------------------------------------
// mma / ldmatrix helpers
// ---------------------------------------------------------------------------
__device__ __forceinline__ void mma16816(float c[4], const uint32_t a[4], const uint32_t b[2]) {
    asm volatile(
        "mma.sync.aligned.m16n8k16.row.col.f32.f16.f16.f32 "
        "{%0,%1,%2,%3}, {%4,%5,%6,%7}, {%8,%9}, {%0,%1,%2,%3};\n"
        : "+f"(c[0]), "+f"(c[1]), "+f"(c[2]), "+f"(c[3])
        : "r"(a[0]), "r"(a[1]), "r"(a[2]), "r"(a[3]), "r"(b[0]), "r"(b[1]));
}

__device__ __forceinline__ void ldsm_x4(uint32_t r[4], uint32_t saddr) {
    asm volatile("ldmatrix.sync.aligned.m8n8.x4.shared.b16 {%0,%1,%2,%3}, [%4];"
                 : "=r"(r[0]), "=r"(r[1]), "=r"(r[2]), "=r"(r[3]) : "r"(saddr));
}
__device__ __forceinline__ void ldsm_x2(uint32_t r[2], uint32_t saddr) {
    asm volatile("ldmatrix.sync.aligned.m8n8.x2.shared.b16 {%0,%1}, [%2];"
                 : "=r"(r[0]), "=r"(r[1]) : "r"(saddr));
}

// legacy scalar frag loads (for the one-shot gemmA kernel)
__device__ __forceinline__ void load_a_frag(uint32_t a[4], const __half* As, int ld,
                                            int row0, int k0, int grp, int qp) {
    const __half* p = As + (row0 + grp) * ld + k0 + qp * 2;
    a[0] = *(const uint32_t*)(p);
    a[1] = *(const uint32_t*)(p + 8 * ld);
    a[2] = *(const uint32_t*)(p + 8);
    a[3] = *(const uint32_t*)(p + 8 * ld + 8);
}
__device__ __forceinline__ void load_b_frag(uint32_t b[2], const __half* Bs, int ld,
                                            int n0, int k0, int grp, int qp) {
    const __half* p = Bs + (n0 + grp) * ld + k0 + qp * 2;
    b[0] = *(const uint32_t*)(p);
    b[1] = *(const uint32_t*)(p + 8);
}

__device__ __forceinline__ float sigf(float x) { return 1.0f / (1.0f + __expf(-x)); }

// cp.async helpers
__device__ __forceinline__ void cp_async16(void* s, const void* g) {
    unsigned sa = (unsigned)__cvta_generic_to_shared(s);
    asm volatile("cp.async.ca.shared.global [%0], [%1], 16;\n" :: "r"(sa), "l"(g));
}
__device__ __forceinline__ void cp_commit() { asm volatile("cp.async.commit_group;\n"); }
__device__ __forceinline__ void cp_wait2()  { asm volatile("cp.async.wait_group 2;\n"); }
__device__ __forceinline__ void cp_wait0()  { asm volatile("cp.async.wait_group 0;\n"); }

// 16-CTA row-group barrier. target = monotonically increasing generation.
__device__ __forceinline__ void group_barrier(int rb, unsigned target) {
    __syncthreads();
    if (threadIdx.x == 0) {
        __threadfence();
        unsigned a = atomicAdd(&d_bars[rb].cnt, 1);
        if (a == 15) {
            d_bars[rb].cnt = 0;
            __threadfence();
            atomicAdd(&d_bars[rb].gen, 1);
        } else {
            unsigned g;
            do {
                __nanosleep(16);
                asm volatile("ld.volatile.global.u32 %0, [%1];" : "=r"(g) : "l"(&d_bars[rb].gen));
            } while (g < target);
        }
        __threadfence();
    }
    __syncthreads();
}

// ---------------------------------------------------------------------------
// prep: weight fusion + fp16 conversions + barrier reset (one launch)
// ---------------------------------------------------------------------------
__global__ void prep_kernel(const float* __restrict__ enc,  const float* __restrict__ ehid,
                            const float* __restrict__ embW, const float* __restrict__ embB,
                            const float* __restrict__ wih,  const float* __restrict__ whh,
                            const float* __restrict__ outW, const float* __restrict__ outB,
                            const float* __restrict__ regW, const float* __restrict__ regB) {
    long long gid0 = (long long)blockIdx.x * blockDim.x + threadIdx.x;
    if (gid0 < 8) { d_bars[gid0].cnt = 0; d_bars[gid0].gen = 0; }

    const long long N0  = (long long)ROWS_ENC * E_;
    const long long N1  = N0 + (long long)B_ * E_;
    const long long N2  = N1 + 1536LL * 1024;
    const long long N3  = N2 + 576LL * 512;
    const long long N3b = N3 + 576;
    const long long N4  = N3b + (long long)O_ * E_;
    const long long N5  = N4 + (long long)B_ * H_;
    const long long N6  = N5 + (long long)H_ * E_;

    for (long long i = gid0; i < N6; i += (long long)gridDim.x * blockDim.x) {
        if (i < N0) {
            d_enc16[i] = __float2half(enc[i]);
        } else if (i < N1) {
            long long k = i - N0; int b = (int)(k >> 8), c = (int)(k & 255);
            d_x0[k] = __float2half(enc[(long long)b * TENC * E_ + 139 * E_ + c]);
        } else if (i < N2) {
            long long k = i - N1; int j = (int)(k >> 10), c = (int)(k & 1023);
            float v = (c < 512) ? wih[j * 512 + c] : whh[j * 512 + c - 512];
            d_Wg[k] = __float2half(v);
        } else if (i < N3) {
            long long k = i - N2; int j = (int)(k >> 9), c = (int)(k & 511);
            float s = 0.f;
            if (j < 512) { for (int m = 0; m < E_; ++m) s += embW[j * E_ + m] * outW[m * H_ + c]; }
            else { int o = j - 512; for (int m = 0; m < E_; ++m) s += regW[o * E_ + m] * outW[m * H_ + c]; }
            d_WA[k] = __float2half(s);
        } else if (i < N3b) {
            int j = (int)(i - N3);
            float s = 0.f;
            if (j < 512) { for (int m = 0; m < E_; ++m) s += embW[j * E_ + m] * outB[m]; s += embB[j]; }
            else { int o = j - 512; for (int m = 0; m < E_; ++m) s += regW[o * E_ + m] * outB[m]; s += regB[o]; }
            d_bA[j] = s;
        } else if (i < N4) {
            long long k = i - N3b; d_regW[k] = __float2half(regW[k]);
        } else if (i < N5) {
            long long k = i - N4; int b = (int)(k >> 9), c = (int)(k & 511);
            float v = ehid[k];
            d_h32[0][k] = v;
            d_eh[0][b * 1024 + 512 + c] = __float2half(v);
        } else {
            long long k = i - N5; d_embW[k] = __float2half(embW[k]);
        }
    }
}

// ---------------------------------------------------------------------------
// Generic fp16 GEMM (one-shot encoder head and e0)
// ---------------------------------------------------------------------------
__global__ __launch_bounds__(256) void gemmA_kernel(
    const __half* __restrict__ A, int lda,
    const __half* __restrict__ Bw, int ldb,
    const float* __restrict__ bias, int K,
    __half* __restrict__ e_out, float* __restrict__ dec_out,
    int t_dec, int enc_mode)
{
    __shared__ __align__(16) __half As[64 * 40];
    __shared__ __align__(16) __half Bs[32 * 40];

    const int tid = threadIdx.x;
    const int m0 = blockIdx.y * 64, n0 = blockIdx.x * 32;
    const int lane = tid & 31, warp = tid >> 5;
    const int wm = warp >> 1, wn = warp & 1;
    const int grp = lane >> 2, qp = lane & 3;

    float c[2][4] = {};
    const int nch = K >> 5;

    for (int kc = 0; kc < nch; ++kc) {
        const int k0 = kc * 32;
        __syncthreads();
        { int r = tid >> 2, v = tid & 3;
          *(uint4*)&As[r * 40 + v * 8] = *(const uint4*)&A[(size_t)(m0 + r) * lda + k0 + v * 8]; }
        if (tid < 128) { int r = tid >> 2, v = tid & 3;
          *(uint4*)&Bs[r * 40 + v * 8] = *(const uint4*)&Bw[(size_t)(n0 + r) * ldb + k0 + v * 8]; }
        __syncthreads();
#pragma unroll
        for (int kk = 0; kk < 32; kk += 16) {
            uint32_t a[4];
            load_a_frag(a, As, 40, wm * 16, kk, grp, qp);
            uint32_t b[2];
            load_b_frag(b, Bs, 40, wn * 16 + 0, kk, grp, qp);
            mma16816(c[0], a, b);
            load_b_frag(b, Bs, 40, wn * 16 + 8, kk, grp, qp);
            mma16816(c[1], a, b);
        }
    }

    const int rbase = m0 + wm * 16 + grp;
    const int cbase = n0 + wn * 16 + qp * 2;
#pragma unroll
    for (int nb = 0; nb < 2; ++nb)
#pragma unroll
        for (int i = 0; i < 4; ++i) {
            int row = rbase + (i >> 1) * 8;
            int col = cbase + nb * 8 + (i & 1);
            float v = c[nb][i] + bias[col];
            if (enc_mode) {
                int b = row / 140, tt = row - b * 140;
                dec_out[(size_t)b * TOUT * O_ + tt * O_ + col] = v;
            } else if (col < H_) {
                e_out[(size_t)row * 1024 + col] = __float2half(fmaxf(v, 0.0f));
            } else {
                dec_out[(size_t)row * TOUT * O_ + t_dec * O_ + (col - H_)] = v;
            }
        }
}

// ---------------------------------------------------------------------------
// Persistent RNN kernel: 128 CTAs (8 row-groups x 16 col-CTAs), weights SMEM-
// resident (XOR swizzle), 4-stage cp.async pipeline in phase B, h in regs.
//
// CTA (rb, cb):
//   Phase B: gates for rows [rb*64,+64), j-cols [cb*32,+32), K=1024 -> h_{t+1}
//   Phase A (cb<12): [e|dec] rows rb, out-cols [cb*48,+48), K=512
// ---------------------------------------------------------------------------
extern __shared__ char smc[];

__global__ __launch_bounds__(256, 1) void persist_kernel(
    const float* __restrict__ bih, const float* __restrict__ bhh,
    const float* __restrict__ ehid, float* __restrict__ out)
{
    const int tid = threadIdx.x;
    const int cid = blockIdx.x;
    const int rb = cid >> 4, cb = cid & 15;
    const int lane = tid & 31, warp = tid >> 5;
    const int wm = warp >> 1, wn = warp & 1;          // 4 x 2 warps
    const int grp = lane >> 2, qp = lane & 3;
    const int m0g = rb * 64;

    char* as0 = smc + WG_BYTES;
    const uint32_t wg_base = (uint32_t)__cvta_generic_to_shared(smc);
    const uint32_t as_base = (uint32_t)__cvta_generic_to_shared(as0);

    // ldsm per-thread constants (XOR swizzle on bits [4:6])
    const int l7x = (lane & 7) << 4;                   // row-dependent XOR
    const uint32_t a_rowb = as_base + (uint32_t)(wm * 16 + (lane & 15)) * 128;
    const int a_cc = (lane >> 4) << 4;                 // 0 / 16 bytes
    const int b_cc = ((lane >> 3) & 1) << 4;
    uint32_t b_rowb[3];
#pragma unroll
    for (int g = 0; g < 3; ++g)
        b_rowb[g] = wg_base + (uint32_t)(g * 32 + wn * 16 + ((lane >> 4) << 3) + (lane & 7)) * 2048;

    // phase-A WA ldsm constants (stage row stride 128B)
    const uint32_t w4_rowoff = (uint32_t)(wn * 24 + ((lane >> 4) << 3) + (lane & 7)) * 128;
    const int l15 = lane & 15;
    const uint32_t w2_rowoff = (uint32_t)(wn * 24 + 16 + (l15 & 7)) * 128;
    const int w2_cc = (l15 >> 3) << 4;

    // cp.async per-thread indices (64-row x 64-half chunk = 512 16B vectors)
    const int ld_r = tid >> 3, ld_v = tid & 7;
    const int ld_r2 = ld_r + 32;

    // ---- Load this CTA's weight slice once (96 rows x 1024 halves, swizzled) ----
    for (int idx = tid; idx < 96 * 128; idx += 256) {
        int r = idx >> 7, v = idx & 127;
        cp_async16(smc + r * 2048 + ((v * 16) ^ ((r & 7) << 4)),
                   &d_Wg[(size_t)((r >> 5) * 512 + cb * 32 + (r & 31)) * 1024 + v * 8]);
    }
    cp_commit(); cp_wait0(); __syncthreads();

    // ---- Per-thread constant registers: biases + resident hidden state ----
    const int rbase = m0g + wm * 16 + grp;
    const int jbase = cb * 32 + wn * 16 + qp * 2;
    float bR4[4], bZ4[4], bNi4[4], bNh4[4];
#pragma unroll
    for (int nb = 0; nb < 2; ++nb)
#pragma unroll
        for (int q = 0; q < 2; ++q) {
            int j = jbase + nb * 8 + q;
            bR4[nb * 2 + q]  = bih[j] + bhh[j];
            bZ4[nb * 2 + q]  = bih[512 + j] + bhh[512 + j];
            bNi4[nb * 2 + q] = bih[1024 + j];
            bNh4[nb * 2 + q] = bhh[1024 + j];
        }
    float hreg[2][4];
#pragma unroll
    for (int nb = 0; nb < 2; ++nb)
#pragma unroll
        for (int i = 0; i < 4; ++i)
            hreg[nb][i] = ehid[(size_t)(rbase + (i >> 1) * 8) * 512 + jbase + nb * 8 + (i & 1)];

    const int n0c = cb * 48;
    const int jl = wn * 24 + qp * 2;
    float bA6[6];
    if (cb < 12) {
#pragma unroll
        for (int nb = 0; nb < 3; ++nb)
#pragma unroll
            for (int q = 0; q < 2; ++q)
                bA6[nb * 2 + q] = d_bA[n0c + jl + nb * 8 + q];
    }

    unsigned gen = 0;
    int cur = 0;
    for (int t = 0; t < NSTEP; ++t) {
        const int nxt = cur ^ 1;

        // ================= Phase B: gate GEMM + GRU epilogue ================
        {
            const __half* A = d_eh[cur];
            float cR[2][4] = {}, cZ[2][4] = {}, cNi[2][4] = {}, cNh[2][4] = {};

            // prologue: stages 0..2
#pragma unroll
            for (int s = 0; s < 3; ++s) {
                char* buf = as0 + s * ASTG_BYTES;
                cp_async16(buf + ld_r * 128 + ((ld_v * 16) ^ ((ld_r & 7) << 4)),
                           &A[(size_t)(m0g + ld_r) * 1024 + s * 64 + ld_v * 8]);
                cp_async16(buf + ld_r2 * 128 + ((ld_v * 16) ^ ((ld_r2 & 7) << 4)),
                           &A[(size_t)(m0g + ld_r2) * 1024 + s * 64 + ld_v * 8]);
                cp_commit();
            }

#pragma unroll 1
            for (int kc = 0; kc < 16; ++kc) {
                cp_wait2();
                __syncthreads();
                if (kc < 13) {
                    char* buf = as0 + ((kc + 3) & 3) * ASTG_BYTES;
                    cp_async16(buf + ld_r * 128 + ((ld_v * 16) ^ ((ld_r & 7) << 4)),
                               &A[(size_t)(m0g + ld_r) * 1024 + (kc + 3) * 64 + ld_v * 8]);
                    cp_async16(buf + ld_r2 * 128 + ((ld_v * 16) ^ ((ld_r2 & 7) << 4)),
                               &A[(size_t)(m0g + ld_r2) * 1024 + (kc + 3) * 64 + ld_v * 8]);
                }
                cp_commit();  // empty groups keep wait_group(2) arithmetic uniform

                const uint32_t ab = a_rowb + (uint32_t)((kc & 3) << 13);
                const int kwb = kc * 128;           // chunk byte offset in weight rows
#pragma unroll
                for (int k4 = 0; k4 < 4; ++k4) {
                    const int kb = k4 * 32;
                    uint32_t a[4], b0[4], b1[4], b2[4];
                    ldsm_x4(a,  ab + (uint32_t)((a_cc + kb) ^ l7x));
                    ldsm_x4(b0, b_rowb[0] + (uint32_t)((b_cc + kwb + kb) ^ l7x));
                    ldsm_x4(b1, b_rowb[1] + (uint32_t)((b_cc + kwb + kb) ^ l7x));
                    ldsm_x4(b2, b_rowb[2] + (uint32_t)((b_cc + kwb + kb) ^ l7x));
                    mma16816(cR[0], a, b0 + 0); mma16816(cR[1], a, b0 + 2);
                    mma16816(cZ[0], a, b1 + 0); mma16816(cZ[1], a, b1 + 2);
                    if (kc < 8) { mma16816(cNi[0], a, b2 + 0); mma16816(cNi[1], a, b2 + 2); }
                    else        { mma16816(cNh[0], a, b2 + 0); mma16816(cNh[1], a, b2 + 2); }
                }
            }

            __half* ehn = d_eh[nxt];
#pragma unroll
            for (int nb = 0; nb < 2; ++nb)
#pragma unroll
                for (int rh = 0; rh < 2; ++rh) {
                    int row = rbase + rh * 8;
                    float hv[2];
#pragma unroll
                    for (int q = 0; q < 2; ++q) {
                        int i = rh * 2 + q;
                        float r = sigf(cR[nb][i] + bR4[nb * 2 + q]);
                        float z = sigf(cZ[nb][i] + bZ4[nb * 2 + q]);
                        float nn = tanhf(cNi[nb][i] + bNi4[nb * 2 + q]
                                         + r * (cNh[nb][i] + bNh4[nb * 2 + q]));
                        hv[q] = (1.0f - z) * nn + z * hreg[nb][i];
                        hreg[nb][i] = hv[q];
                    }
                    *(__half2*)&ehn[(size_t)row * 1024 + 512 + jbase + nb * 8] =
                        __floats2half2_rn(hv[0], hv[1]);
                }
        }
        ++gen; group_barrier(rb, gen);

        // ============ Phase A: [e|dec] = h_{t+1} @ WA^T + bA ================
        if (cb < 12) {
            const __half* Ah = &d_eh[nxt][512];   // h half, row stride 1024
            float cc[3][4] = {};
            char* wstg = as0 + 2 * ASTG_BYTES;    // WA stages at +16K (2 x 6KB)
            const uint32_t w_base = as_base + 2 * ASTG_BYTES;

            // prologue chunk 0 (A + WA)
            {
                cp_async16(as0 + ld_r * 128 + ((ld_v * 16) ^ ((ld_r & 7) << 4)),
                           &Ah[(size_t)(m0g + ld_r) * 1024 + ld_v * 8]);
                cp_async16(as0 + ld_r2 * 128 + ((ld_v * 16) ^ ((ld_r2 & 7) << 4)),
                           &Ah[(size_t)(m0g + ld_r2) * 1024 + ld_v * 8]);
                for (int idx = tid; idx < 384; idx += 256) {
                    int r = idx >> 3, v = idx & 7;
                    cp_async16(wstg + r * 128 + ((v * 16) ^ ((r & 7) << 4)),
                               &d_WA[(size_t)(cb * 48 + r) * 512 + v * 8]);
                }
                cp_commit();
            }

#pragma unroll 1
            for (int kc = 0; kc < 8; ++kc) {
                cp_wait0();
                __syncthreads();
                if (kc < 7) {
                    char* abuf = as0 + ((kc + 1) & 1) * ASTG_BYTES;
                    char* wbuf = wstg + ((kc + 1) & 1) * 6144;
                    cp_async16(abuf + ld_r * 128 + ((ld_v * 16) ^ ((ld_r & 7) << 4)),
                               &Ah[(size_t)(m0g + ld_r) * 1024 + (kc + 1) * 64 + ld_v * 8]);
                    cp_async16(abuf + ld_r2 * 128 + ((ld_v * 16) ^ ((ld_r2 & 7) << 4)),
                               &Ah[(size_t)(m0g + ld_r2) * 1024 + (kc + 1) * 64 + ld_v * 8]);
                    for (int idx = tid; idx < 384; idx += 256) {
                        int r = idx >> 3, v = idx & 7;
                        cp_async16(wbuf + r * 128 + ((v * 16) ^ ((r & 7) << 4)),
                                   &d_WA[(size_t)(cb * 48 + r) * 512 + (kc + 1) * 64 + v * 8]);
                    }
                }
                cp_commit();

                const uint32_t ab = a_rowb + (uint32_t)((kc & 1) << 13);
                const uint32_t wb = w_base + (uint32_t)((kc & 1) * 6144);
#pragma unroll
                for (int k4 = 0; k4 < 4; ++k4) {
                    const int kb = k4 * 32;
                    uint32_t a[4], w4[4], w2[2];
                    ldsm_x4(a,  ab + (uint32_t)((a_cc + kb) ^ l7x));
                    ldsm_x4(w4, wb + w4_rowoff + (uint32_t)((b_cc + kb) ^ l7x));
                    ldsm_x2(w2, wb + w2_rowoff + (uint32_t)((w2_cc + kb) ^ l7x));
                    mma16816(cc[0], a, w4 + 0);
                    mma16816(cc[1], a, w4 + 2);
                    mma16816(cc[2], a, w2);
                }
            }

            __half* ehn = d_eh[nxt];
#pragma unroll
            for (int nb = 0; nb < 3; ++nb)
#pragma unroll
                for (int rh = 0; rh < 2; ++rh) {
                    int row = rbase + rh * 8;
                    int j0 = n0c + jl + nb * 8;    // even; pairs never straddle 512
                    float v0 = cc[nb][rh * 2 + 0] + bA6[nb * 2 + 0];
                    float v1 = cc[nb][rh * 2 + 1] + bA6[nb * 2 + 1];
                    if (j0 < 512) {
                        *(__half2*)&ehn[(size_t)row * 1024 + j0] =
                            __floats2half2_rn(fmaxf(v0, 0.0f), fmaxf(v1, 0.0f));
                    } else {
                        *(float2*)&out[(size_t)row * TOUT * O_ + (140 + t) * O_ + (j0 - 512)] =
                            make_float2(v0, v1);
                    }
                }
        }
        ++gen; group_barrier(rb, gen);

        cur = nxt;
    }
}

// ---------------------------------------------------------------------------
// Launch sequence (graph-capturable, default stream)
// ---------------------------------------------------------------------------
extern "C" void kernel_launch(void* const* d_in, const int* in_sizes, int n_in,
                              void* d_out, int out_size) {
    const float* enc  = (const float*)d_in[0];
    const float* ehid = (const float*)d_in[1];
    const float* embW = (const float*)d_in[2];
    const float* embB = (const float*)d_in[3];
    const float* wih  = (const float*)d_in[4];
    const float* whh  = (const float*)d_in[5];
    const float* bih  = (const float*)d_in[6];
    const float* bhh  = (const float*)d_in[7];
    const float* outW = (const float*)d_in[8];
    const float* outB = (const float*)d_in[9];
    const float* regW = (const float*)d_in[10];
    const float* regB = (const float*)d_in[11];
    float* out = (float*)d_out;

    void* sym;
    cudaGetSymbolAddress(&sym, d_eh);    __half* p_eh   = (__half*)sym;
    cudaGetSymbolAddress(&sym, d_x0);    __half* p_x0   = (__half*)sym;
    cudaGetSymbolAddress(&sym, d_embW);  __half* p_embW = (__half*)sym;
    cudaGetSymbolAddress(&sym, d_regW);  __half* p_regW = (__half*)sym;
    cudaGetSymbolAddress(&sym, d_enc16); __half* p_enc  = (__half*)sym;

    cudaFuncSetAttribute(persist_kernel,
                         cudaFuncAttributeMaxDynamicSharedMemorySize, SMEM_TOTAL_BYTES);

    // 1) Prep: conversions + weight fusion + barrier reset
    prep_kernel<<<4096, 256>>>(enc, ehid, embW, embB, wih, whh, outW, outB, regW, regB);

    // 2) Encoder regression head: out[:, 0:140, :]
    gemmA_kernel<<<dim3(2, 1120), 256>>>(p_enc, E_, p_regW, E_, regB, E_,
                                         nullptr, out, 0, 1);

    // 3) Step 0: e0 = relu(x0 @ emb_W^T + emb_b)
    gemmA_kernel<<<dim3(16, 8), 256>>>(p_x0, E_, p_embW, E_, embB, E_,
                                       p_eh, nullptr, 0, 0);

    // 4) All 140 GRU steps in one persistent kernel (128 CTAs, 1/SM)
    persist_kernel<<<128, 256, SMEM_TOTAL_BYTES>>>(bih, bhh, ehid, out);
}

// round 6
// speedup vs baseline: 1.2743x; 1.0324x over previous
#include <cuda_runtime.h>
#include <cuda_fp16.h>
#include <math.h>
#include <stdint.h>

// Problem constants
#define B_    512
#define TENC  140
#define E_    256
#define H_    512
#define O_    64
#define TOUT  280
#define NSTEP 140
#define ROWS_ENC (B_*TENC)   // 71680

// Persistent kernel: 128 CTAs = 8 row-groups x 16 col-CTAs, 1 CTA/SM
#define WG_BYTES   (96 * 2048)              // 196608: 3 gates x 32 j-rows x 1024 halves (swizzled)
#define AW_BYTES   4096                     // per-warp A buffer: 2 stages x (16 rows x 64 halves)
#define SMEM_TOTAL_BYTES (WG_BYTES + 8 * AW_BYTES)   // 229376

// ---------------------------------------------------------------------------
// Device scratch (static globals; no runtime allocation allowed)
// ---------------------------------------------------------------------------
__device__ __half d_eh[2][B_ * 1024];        // [buf][row][0:512 e | 512:1024 h] fp16
__device__ float  d_h32[2][B_ * H_];         // (init only)
__device__ __half d_Wg[3 * H_ * 1024];       // 1536 x 1024: [w_ih | w_hh] fused by K
__device__ __half d_WA[(H_ + O_) * H_];      // 576 x 512: [emb_W@out_W ; reg_W@out_W]
__device__ float  d_bA[H_ + O_];             // fused biases
__device__ __half d_x0[B_ * E_];             // x0 = encoder_outputs[:, -1, :] fp16
__device__ __half d_embW[H_ * E_];           // emb_W fp16 (step-0 path)
__device__ __half d_regW[O_ * E_];           // reg_W fp16 (encoder head)
__device__ __half d_enc16[(size_t)ROWS_ENC * E_]; // encoder outputs fp16

// Row-group barriers (8 groups of 16 CTAs), one cache line each
struct Bar { unsigned cnt; unsigned gen; unsigned pad[30]; };
__device__ Bar d_bars[8];

// ---------------------------------------------------------------------------
// mma / ldmatrix helpers
// ---------------------------------------------------------------------------
__device__ __forceinline__ void mma16816(float c[4], const uint32_t a[4], const uint32_t b[2]) {
    asm volatile(
        "mma.sync.aligned.m16n8k16.row.col.f32.f16.f16.f32 "
        "{%0,%1,%2,%3}, {%4,%5,%6,%7}, {%8,%9}, {%0,%1,%2,%3};\n"
        : "+f"(c[0]), "+f"(c[1]), "+f"(c[2]), "+f"(c[3])
        : "r"(a[0]), "r"(a[1]), "r"(a[2]), "r"(a[3]), "r"(b[0]), "r"(b[1]));
}

__device__ __forceinline__ void ldsm_x4(uint32_t r[4], uint32_t saddr) {
    asm volatile("ldmatrix.sync.aligned.m8n8.x4.shared.b16 {%0,%1,%2,%3}, [%4];"
                 : "=r"(r[0]), "=r"(r[1]), "=r"(r[2]), "=r"(r[3]) : "r"(saddr));
}

// legacy scalar frag loads (for the one-shot gemmA kernel)
__device__ __forceinline__ void load_a_frag(uint32_t a[4], const __half* As, int ld,
                                            int row0, int k0, int grp, int qp) {
    const __half* p = As + (row0 + grp) * ld + k0 + qp * 2;
    a[0] = *(const uint32_t*)(p);
    a[1] = *(const uint32_t*)(p + 8 * ld);
    a[2] = *(const uint32_t*)(p + 8);
    a[3] = *(const uint32_t*)(p + 8 * ld + 8);
}
__device__ __forceinline__ void load_b_frag(uint32_t b[2], const __half* Bs, int ld,
                                            int n0, int k0, int grp, int qp) {
    const __half* p = Bs + (n0 + grp) * ld + k0 + qp * 2;
    b[0] = *(const uint32_t*)(p);
    b[1] = *(const uint32_t*)(p + 8);
}

__device__ __forceinline__ float sigf(float x) { return 1.0f / (1.0f + __expf(-x)); }

// cp.async helpers
__device__ __forceinline__ void cp_async16(void* s, const void* g) {
    unsigned sa = (unsigned)__cvta_generic_to_shared(s);
    asm volatile("cp.async.ca.shared.global [%0], [%1], 16;\n" :: "r"(sa), "l"(g));
}
__device__ __forceinline__ void cp_commit() { asm volatile("cp.async.commit_group;\n"); }
__device__ __forceinline__ void cp_wait1()  { asm volatile("cp.async.wait_group 1;\n"); }
__device__ __forceinline__ void cp_wait0()  { asm volatile("cp.async.wait_group 0;\n"); }

// 16-CTA row-group barrier. target = monotonically increasing generation.
__device__ __forceinline__ void group_barrier(int rb, unsigned target) {
    __syncthreads();
    if (threadIdx.x == 0) {
        __threadfence();
        unsigned a = atomicAdd(&d_bars[rb].cnt, 1);
        if (a == 15) {
            d_bars[rb].cnt = 0;
            __threadfence();
            atomicAdd(&d_bars[rb].gen, 1);
        } else {
            unsigned g;
            do {
                __nanosleep(16);
                asm volatile("ld.volatile.global.u32 %0, [%1];" : "=r"(g) : "l"(&d_bars[rb].gen));
            } while (g < target);
        }
        __threadfence();
    }
    __syncthreads();
}

// ---------------------------------------------------------------------------
// prep: weight fusion + fp16 conversions + barrier reset (one launch)
// ---------------------------------------------------------------------------
__global__ void prep_kernel(const float* __restrict__ enc,  const float* __restrict__ ehid,
                            const float* __restrict__ embW, const float* __restrict__ embB,
                            const float* __restrict__ wih,  const float* __restrict__ whh,
                            const float* __restrict__ outW, const float* __restrict__ outB,
                            const float* __restrict__ regW, const float* __restrict__ regB) {
    long long gid0 = (long long)blockIdx.x * blockDim.x + threadIdx.x;
    if (gid0 < 8) { d_bars[gid0].cnt = 0; d_bars[gid0].gen = 0; }

    const long long N0  = (long long)ROWS_ENC * E_;
    const long long N1  = N0 + (long long)B_ * E_;
    const long long N2  = N1 + 1536LL * 1024;
    const long long N3  = N2 + 576LL * 512;
    const long long N3b = N3 + 576;
    const long long N4  = N3b + (long long)O_ * E_;
    const long long N5  = N4 + (long long)B_ * H_;
    const long long N6  = N5 + (long long)H_ * E_;

    for (long long i = gid0; i < N6; i += (long long)gridDim.x * blockDim.x) {
        if (i < N0) {
            d_enc16[i] = __float2half(enc[i]);
        } else if (i < N1) {
            long long k = i - N0; int b = (int)(k >> 8), c = (int)(k & 255);
            d_x0[k] = __float2half(enc[(long long)b * TENC * E_ + 139 * E_ + c]);
        } else if (i < N2) {
            long long k = i - N1; int j = (int)(k >> 10), c = (int)(k & 1023);
            float v = (c < 512) ? wih[j * 512 + c] : whh[j * 512 + c - 512];
            d_Wg[k] = __float2half(v);
        } else if (i < N3) {
            long long k = i - N2; int j = (int)(k >> 9), c = (int)(k & 511);
            float s = 0.f;
            if (j < 512) { for (int m = 0; m < E_; ++m) s += embW[j * E_ + m] * outW[m * H_ + c]; }
            else { int o = j - 512; for (int m = 0; m < E_; ++m) s += regW[o * E_ + m] * outW[m * H_ + c]; }
            d_WA[k] = __float2half(s);
        } else if (i < N3b) {
            int j = (int)(i - N3);
            float s = 0.f;
            if (j < 512) { for (int m = 0; m < E_; ++m) s += embW[j * E_ + m] * outB[m]; s += embB[j]; }
            else { int o = j - 512; for (int m = 0; m < E_; ++m) s += regW[o * E_ + m] * outB[m]; s += regB[o]; }
            d_bA[j] = s;
        } else if (i < N4) {
            long long k = i - N3b; d_regW[k] = __float2half(regW[k]);
        } else if (i < N5) {
            long long k = i - N4; int b = (int)(k >> 9), c = (int)(k & 511);
            float v = ehid[k];
            d_h32[0][k] = v;
            d_eh[0][b * 1024 + 512 + c] = __float2half(v);
        } else {
            long long k = i - N5; d_embW[k] = __float2half(embW[k]);
        }
    }
}

// ---------------------------------------------------------------------------
// Generic fp16 GEMM (one-shot encoder head and e0)
// ---------------------------------------------------------------------------
__global__ __launch_bounds__(256) void gemmA_kernel(
    const __half* __restrict__ A, int lda,
    const __half* __restrict__ Bw, int ldb,
    const float* __restrict__ bias, int K,
    __half* __restrict__ e_out, float* __restrict__ dec_out,
    int t_dec, int enc_mode)
{
    __shared__ __align__(16) __half As[64 * 40];
    __shared__ __align__(16) __half Bs[32 * 40];

    const int tid = threadIdx.x;
    const int m0 = blockIdx.y * 64, n0 = blockIdx.x * 32;
    const int lane = tid & 31, warp = tid >> 5;
    const int wm = warp >> 1, wn = warp & 1;
    const int grp = lane >> 2, qp = lane & 3;

    float c[2][4] = {};
    const int nch = K >> 5;

    for (int kc = 0; kc < nch; ++kc) {
        const int k0 = kc * 32;
        __syncthreads();
        { int r = tid >> 2, v = tid & 3;
          *(uint4*)&As[r * 40 + v * 8] = *(const uint4*)&A[(size_t)(m0 + r) * lda + k0 + v * 8]; }
        if (tid < 128) { int r = tid >> 2, v = tid & 3;
          *(uint4*)&Bs[r * 40 + v * 8] = *(const uint4*)&Bw[(size_t)(n0 + r) * ldb + k0 + v * 8]; }
        __syncthreads();
#pragma unroll
        for (int kk = 0; kk < 32; kk += 16) {
            uint32_t a[4];
            load_a_frag(a, As, 40, wm * 16, kk, grp, qp);
            uint32_t b[2];
            load_b_frag(b, Bs, 40, wn * 16 + 0, kk, grp, qp);
            mma16816(c[0], a, b);
            load_b_frag(b, Bs, 40, wn * 16 + 8, kk, grp, qp);
            mma16816(c[1], a, b);
        }
    }

    const int rbase = m0 + wm * 16 + grp;
    const int cbase = n0 + wn * 16 + qp * 2;
#pragma unroll
    for (int nb = 0; nb < 2; ++nb)
#pragma unroll
        for (int i = 0; i < 4; ++i) {
            int row = rbase + (i >> 1) * 8;
            int col = cbase + nb * 8 + (i & 1);
            float v = c[nb][i] + bias[col];
            if (enc_mode) {
                int b = row / 140, tt = row - b * 140;
                dec_out[(size_t)b * TOUT * O_ + tt * O_ + col] = v;
            } else if (col < H_) {
                e_out[(size_t)row * 1024 + col] = __float2half(fmaxf(v, 0.0f));
            } else {
                dec_out[(size_t)row * TOUT * O_ + t_dec * O_ + (col - H_)] = v;
            }
        }
}

// ---------------------------------------------------------------------------
// Persistent RNN kernel: 128 CTAs (8 row-groups x 16 col-CTAs), weights SMEM-
// resident (XOR swizzle). Warp-decoupled mainloops: each warp owns a private
// 2-stage cp.async A-buffer (its 16 rows only) -> ZERO bar.sync in mainloops.
//
// CTA (rb, cb):
//   Phase B: gates for rows [rb*64,+64), j-cols [cb*32,+32), K=1024 -> h_{t+1}
//   Phase A (cb<12): [e|dec] rows rb, out-cols [cb*48,+48), K=512 (WA via LDG)
// ---------------------------------------------------------------------------
extern __shared__ char smc[];

__global__ __launch_bounds__(256, 1) void persist_kernel(
    const float* __restrict__ bih, const float* __restrict__ bhh,
    const float* __restrict__ ehid, float* __restrict__ out)
{
    const int tid = threadIdx.x;
    const int cid = blockIdx.x;
    const int rb = cid >> 4, cb = cid & 15;
    const int lane = tid & 31, warp = tid >> 5;
    const int wm = warp >> 1, wn = warp & 1;          // 4 x 2 warps
    const int grp = lane >> 2, qp = lane & 3;
    const int m0g = rb * 64;
    const int arow0 = m0g + wm * 16;                  // this warp's 16 A rows

    char* aw = smc + WG_BYTES + warp * AW_BYTES;      // per-warp A buffer (2 stages)
    const uint32_t wg_base = (uint32_t)__cvta_generic_to_shared(smc);
    const uint32_t aw_base = (uint32_t)__cvta_generic_to_shared(aw);

    // ldsm per-thread constants (XOR swizzle on bits [4:6])
    const int l7x = (lane & 7) << 4;
    const uint32_t a_rowb = aw_base + (uint32_t)(lane & 15) * 128;
    const int a_cc = (lane >> 4) << 4;                 // 0 / 16 bytes
    const int b_cc = ((lane >> 3) & 1) << 4;
    uint32_t b_rowb[3];
#pragma unroll
    for (int g = 0; g < 3; ++g)
        b_rowb[g] = wg_base + (uint32_t)(g * 32 + wn * 16 + ((lane >> 4) << 3) + (lane & 7)) * 2048;

    // per-warp cp.async lane mapping (16 rows x 64 halves = 128 vec; 4 per lane)
    // idx = lane + 32*i : r = idx>>3 (0..15), v = idx&7

    // ---- Load this CTA's weight slice once (96 rows x 1024 halves, swizzled) ----
    for (int idx = tid; idx < 96 * 128; idx += 256) {
        int r = idx >> 7, v = idx & 127;
        cp_async16(smc + r * 2048 + ((v * 16) ^ ((r & 7) << 4)),
                   &d_Wg[(size_t)((r >> 5) * 512 + cb * 32 + (r & 31)) * 1024 + v * 8]);
    }
    cp_commit(); cp_wait0(); __syncthreads();

    // ---- Per-thread constant registers: biases + resident hidden state ----
    const int rbase = m0g + wm * 16 + grp;
    const int jbase = cb * 32 + wn * 16 + qp * 2;
    float bR4[4], bZ4[4], bNi4[4], bNh4[4];
#pragma unroll
    for (int nb = 0; nb < 2; ++nb)
#pragma unroll
        for (int q = 0; q < 2; ++q) {
            int j = jbase + nb * 8 + q;
            bR4[nb * 2 + q]  = bih[j] + bhh[j];
            bZ4[nb * 2 + q]  = bih[512 + j] + bhh[512 + j];
            bNi4[nb * 2 + q] = bih[1024 + j];
            bNh4[nb * 2 + q] = bhh[1024 + j];
        }
    float hreg[2][4];
#pragma unroll
    for (int nb = 0; nb < 2; ++nb)
#pragma unroll
        for (int i = 0; i < 4; ++i)
            hreg[nb][i] = ehid[(size_t)(rbase + (i >> 1) * 8) * 512 + jbase + nb * 8 + (i & 1)];

    const int n0c = cb * 48;
    const int jl = wn * 24 + qp * 2;
    float bA6[6];
    const __half* pwc[3];
    if (cb < 12) {
#pragma unroll
        for (int nb = 0; nb < 3; ++nb) {
#pragma unroll
            for (int q = 0; q < 2; ++q)
                bA6[nb * 2 + q] = d_bA[n0c + jl + nb * 8 + q];
            pwc[nb] = d_WA + (size_t)(n0c + wn * 24 + nb * 8 + grp) * 512 + qp * 2;
        }
    }

    unsigned gen = 0;
    int cur = 0;
    for (int t = 0; t < NSTEP; ++t) {
        const int nxt = cur ^ 1;

        // ================= Phase B: gate GEMM + GRU epilogue ================
        {
            const __half* Asrc = d_eh[cur];
            float cR[2][4] = {}, cZ[2][4] = {}, cNi[2][4] = {}, cNh[2][4] = {};

            // prologue: chunks 0,1 -> stages 0,1 (per warp)
#pragma unroll
            for (int s = 0; s < 2; ++s) {
#pragma unroll
                for (int i = 0; i < 4; ++i) {
                    int idx = lane + 32 * i, r = idx >> 3, v = idx & 7;
                    cp_async16(aw + s * 2048 + r * 128 + ((v * 16) ^ ((r & 7) << 4)),
                               &Asrc[(size_t)(arow0 + r) * 1024 + s * 64 + v * 8]);
                }
                cp_commit();
            }

#pragma unroll 1
            for (int kc = 0; kc < 16; ++kc) {
                cp_wait1();                              // per-warp: chunk kc ready
                const uint32_t ab = a_rowb + (uint32_t)((kc & 1) << 11);
                const int kwb = kc * 128;                // chunk byte offset in weight rows
#pragma unroll
                for (int k4 = 0; k4 < 4; ++k4) {
                    const int kb = k4 * 32;
                    uint32_t a[4], b0[4], b1[4], b2[4];
                    ldsm_x4(a,  ab + (uint32_t)((a_cc + kb) ^ l7x));
                    ldsm_x4(b0, b_rowb[0] + (uint32_t)((b_cc + kwb + kb) ^ l7x));
                    ldsm_x4(b1, b_rowb[1] + (uint32_t)((b_cc + kwb + kb) ^ l7x));
                    ldsm_x4(b2, b_rowb[2] + (uint32_t)((b_cc + kwb + kb) ^ l7x));
                    mma16816(cR[0], a, b0 + 0); mma16816(cR[1], a, b0 + 2);
                    mma16816(cZ[0], a, b1 + 0); mma16816(cZ[1], a, b1 + 2);
                    if (kc < 8) { mma16816(cNi[0], a, b2 + 0); mma16816(cNi[1], a, b2 + 2); }
                    else        { mma16816(cNh[0], a, b2 + 0); mma16816(cNh[1], a, b2 + 2); }
                }
                if (kc < 14) {                           // issue chunk kc+2 into freed stage
#pragma unroll
                    for (int i = 0; i < 4; ++i) {
                        int idx = lane + 32 * i, r = idx >> 3, v = idx & 7;
                        cp_async16(aw + ((kc & 1) << 11) + r * 128 + ((v * 16) ^ ((r & 7) << 4)),
                                   &Asrc[(size_t)(arow0 + r) * 1024 + (kc + 2) * 64 + v * 8]);
                    }
                }
                cp_commit();                             // (possibly empty) keeps wait arithmetic uniform
            }

            __half* ehn = d_eh[nxt];
#pragma unroll
            for (int nb = 0; nb < 2; ++nb)
#pragma unroll
                for (int rh = 0; rh < 2; ++rh) {
                    int row = rbase + rh * 8;
                    float hv[2];
#pragma unroll
                    for (int q = 0; q < 2; ++q) {
                        int i = rh * 2 + q;
                        float r = sigf(cR[nb][i] + bR4[nb * 2 + q]);
                        float z = sigf(cZ[nb][i] + bZ4[nb * 2 + q]);
                        float nn = tanhf(cNi[nb][i] + bNi4[nb * 2 + q]
                                         + r * (cNh[nb][i] + bNh4[nb * 2 + q]));
                        hv[q] = (1.0f - z) * nn + z * hreg[nb][i];
                        hreg[nb][i] = hv[q];
                    }
                    *(__half2*)&ehn[(size_t)row * 1024 + 512 + jbase + nb * 8] =
                        __floats2half2_rn(hv[0], hv[1]);
                }
        }
        ++gen; group_barrier(rb, gen);

        // ============ Phase A: [e|dec] = h_{t+1} @ WA^T + bA ================
        if (cb < 12) {
            const __half* Ah = &d_eh[nxt][512];   // h half, row stride 1024
            float cc[3][4] = {};
            uint32_t Breg[2][4][6];

            // prologue: A chunks 0,1 -> stages 0,1; WA chunk 0 frags -> Breg[0]
#pragma unroll
            for (int s = 0; s < 2; ++s) {
#pragma unroll
                for (int i = 0; i < 4; ++i) {
                    int idx = lane + 32 * i, r = idx >> 3, v = idx & 7;
                    cp_async16(aw + s * 2048 + r * 128 + ((v * 16) ^ ((r & 7) << 4)),
                               &Ah[(size_t)(arow0 + r) * 1024 + s * 64 + v * 8]);
                }
                cp_commit();
            }
#pragma unroll
            for (int k4 = 0; k4 < 4; ++k4)
#pragma unroll
                for (int nb = 0; nb < 3; ++nb) {
                    Breg[0][k4][nb * 2 + 0] = *(const uint32_t*)&pwc[nb][k4 * 16];
                    Breg[0][k4][nb * 2 + 1] = *(const uint32_t*)&pwc[nb][k4 * 16 + 8];
                }

#pragma unroll 1
            for (int kc = 0; kc < 8; ++kc) {
                cp_wait1();
                const int cbuf = kc & 1, nbuf = cbuf ^ 1;
                if (kc < 7) {                            // prefetch next WA frags (regs)
#pragma unroll
                    for (int k4 = 0; k4 < 4; ++k4)
#pragma unroll
                        for (int nb = 0; nb < 3; ++nb) {
                            Breg[nbuf][k4][nb * 2 + 0] =
                                *(const uint32_t*)&pwc[nb][(kc + 1) * 64 + k4 * 16];
                            Breg[nbuf][k4][nb * 2 + 1] =
                                *(const uint32_t*)&pwc[nb][(kc + 1) * 64 + k4 * 16 + 8];
                        }
                }
                const uint32_t ab = a_rowb + (uint32_t)(cbuf << 11);
#pragma unroll
                for (int k4 = 0; k4 < 4; ++k4) {
                    const int kb = k4 * 32;
                    uint32_t a[4];
                    ldsm_x4(a, ab + (uint32_t)((a_cc + kb) ^ l7x));
                    mma16816(cc[0], a, &Breg[cbuf][k4][0]);
                    mma16816(cc[1], a, &Breg[cbuf][k4][2]);
                    mma16816(cc[2], a, &Breg[cbuf][k4][4]);
                }
                if (kc < 6) {                            // issue A chunk kc+2
#pragma unroll
                    for (int i = 0; i < 4; ++i) {
                        int idx = lane + 32 * i, r = idx >> 3, v = idx & 7;
                        cp_async16(aw + (cbuf << 11) + r * 128 + ((v * 16) ^ ((r & 7) << 4)),
                                   &Ah[(size_t)(arow0 + r) * 1024 + (kc + 2) * 64 + v * 8]);
                    }
                }
                cp_commit();
            }

            __half* ehn = d_eh[nxt];
#pragma unroll
            for (int nb = 0; nb < 3; ++nb)
#pragma unroll
                for (int rh = 0; rh < 2; ++rh) {
                    int row = rbase + rh * 8;
                    int j0 = n0c + jl + nb * 8;    // even; pairs never straddle 512
                    float v0 = cc[nb][rh * 2 + 0] + bA6[nb * 2 + 0];
                    float v1 = cc[nb][rh * 2 + 1] + bA6[nb * 2 + 1];
                    if (j0 < 512) {
                        *(__half2*)&ehn[(size_t)row * 1024 + j0] =
                            __floats2half2_rn(fmaxf(v0, 0.0f), fmaxf(v1, 0.0f));
                    } else {
                        *(float2*)&out[(size_t)row * TOUT * O_ + (140 + t) * O_ + (j0 - 512)] =
                            make_float2(v0, v1);
                    }
                }
        }
        ++gen; group_barrier(rb, gen);

        cur = nxt;
    }
}

// ---------------------------------------------------------------------------
// Launch sequence (graph-capturable, default stream)
// ---------------------------------------------------------------------------
extern "C" void kernel_launch(void* const* d_in, const int* in_sizes, int n_in,
                              void* d_out, int out_size) {
    const float* enc  = (const float*)d_in[0];
    const float* ehid = (const float*)d_in[1];
    const float* embW = (const float*)d_in[2];
    const float* embB = (const float*)d_in[3];
    const float* wih  = (const float*)d_in[4];
    const float* whh  = (const float*)d_in[5];
    const float* bih  = (const float*)d_in[6];
    const float* bhh  = (const float*)d_in[7];
    const float* outW = (const float*)d_in[8];
    const float* outB = (const float*)d_in[9];
    const float* regW = (const float*)d_in[10];
    const float* regB = (const float*)d_in[11];
    float* out = (float*)d_out;

    void* sym;
    cudaGetSymbolAddress(&sym, d_eh);    __half* p_eh   = (__half*)sym;
    cudaGetSymbolAddress(&sym, d_x0);    __half* p_x0   = (__half*)sym;
    cudaGetSymbolAddress(&sym, d_embW);  __half* p_embW = (__half*)sym;
    cudaGetSymbolAddress(&sym, d_regW);  __half* p_regW = (__half*)sym;
    cudaGetSymbolAddress(&sym, d_enc16); __half* p_enc  = (__half*)sym;

    cudaFuncSetAttribute(persist_kernel,
                         cudaFuncAttributeMaxDynamicSharedMemorySize, SMEM_TOTAL_BYTES);

    // 1) Prep: conversions + weight fusion + barrier reset
    prep_kernel<<<4096, 256>>>(enc, ehid, embW, embB, wih, whh, outW, outB, regW, regB);

    // 2) Encoder regression head: out[:, 0:140, :]
    gemmA_kernel<<<dim3(2, 1120), 256>>>(p_enc, E_, p_regW, E_, regB, E_,
                                         nullptr, out, 0, 1);

    // 3) Step 0: e0 = relu(x0 @ emb_W^T + emb_b)
    gemmA_kernel<<<dim3(16, 8), 256>>>(p_x0, E_, p_embW, E_, embB, E_,
                                       p_eh, nullptr, 0, 0);

    // 4) All 140 GRU steps in one persistent kernel (128 CTAs, 1/SM)
    persist_kernel<<<128, 256, SMEM_TOTAL_BYTES>>>(bih, bhh, ehid, out);
}